// round 3
// baseline (speedup 1.0000x reference)
#include <cuda_runtime.h>
#include <math.h>

#define BINS 50
#define MBINS (BINS * BINS)                  // 2500
#define JBINS (BINS * BINS * BINS * BINS)    // 6,250,000
#define MH_BLOCKS 64                         // marginal-hist blocks inside phase2
#define P2_BLOCKS 1184                       // total blocks of phase2
#define EJ_BLOCKS 1184

// ---------------- device scratch (no allocations allowed) ----------------
// All state is restored to these initial values by the end of every
// kernel_launch execution (clear-on-read), so each graph replay is identical.
__device__ double   g_sums[14] = {};   // 0..3 sum x_i ; 4..13 upper-tri sum x_i x_j
__device__ double   g_entJ = 0.0;      // sum c*log(c) over joint hist
__device__ unsigned g_minq = 0xFFFFFFFFu, g_maxq = 0u;
__device__ unsigned g_minr = 0xFFFFFFFFu, g_maxr = 0u;
__device__ unsigned g_mins = 0xFFFFFFFFu, g_maxs = 0u;
__device__ unsigned g_done = 0;
__device__ unsigned g_hist_joint[JBINS];   // 25 MB, starts zero, kept zero
__device__ unsigned g_hist_q[MBINS];
__device__ unsigned g_hist_r[MBINS];

// ---------------- helpers ----------------
__device__ __forceinline__ unsigned fenc(float f) {
    unsigned u = __float_as_uint(f);
    return (u & 0x80000000u) ? ~u : (u | 0x80000000u);
}
__device__ __forceinline__ float fdec(unsigned e) {
    unsigned u = (e & 0x80000000u) ? (e & 0x7fffffffu) : ~e;
    return __uint_as_float(u);
}
__device__ __forceinline__ int binof(float x, float lo, float scale) {
    int i = (int)floorf((x - lo) * scale);
    i = i < 0 ? 0 : i;
    return i > (BINS - 1) ? (BINS - 1) : i;
}

// Compute mean + 4x4 lower Cholesky from g_sums. One thread.
// out[0..9]  = l00,l10,l11,l20,l21,l22,l30,l31,l32,l33
// out[10..13] = mean
__device__ void chol_from_sums(float* out, double nn) {
    double shs[14];
#pragma unroll
    for (int k = 0; k < 14; k++) shs[k] = g_sums[k];
    double mean[4];
#pragma unroll
    for (int i = 0; i < 4; i++) mean[i] = shs[i] / nn;
    float cov[4][4];
    int idx = 4;
#pragma unroll
    for (int i = 0; i < 4; i++)
#pragma unroll
        for (int j = i; j < 4; j++) {
            float c = (float)((shs[idx++] - nn * mean[i] * mean[j]) / (nn - 1.0));
            cov[i][j] = c; cov[j][i] = c;
        }
#pragma unroll
    for (int i = 0; i < 4; i++) cov[i][i] += 1e-6f;

    float L[4][4] = {};
#pragma unroll
    for (int j = 0; j < 4; j++) {
        float d = cov[j][j];
#pragma unroll
        for (int k = 0; k < 4; k++) if (k < j) d -= L[j][k] * L[j][k];
        float dj = sqrtf(d);
        L[j][j] = dj;
        float inv = __frcp_rn(dj);
#pragma unroll
        for (int i = 0; i < 4; i++) if (i > j) {
            float v = cov[i][j];
#pragma unroll
            for (int k = 0; k < 4; k++) if (k < j) v -= L[i][k] * L[j][k];
            L[i][j] = v * inv;
        }
    }
    out[0] = L[0][0];
    out[1] = L[1][0]; out[2] = L[1][1];
    out[3] = L[2][0]; out[4] = L[2][1]; out[5] = L[2][2];
    out[6] = L[3][0]; out[7] = L[3][1]; out[8] = L[3][2]; out[9] = L[3][3];
#pragma unroll
    for (int i = 0; i < 4; i++) out[10 + i] = (float)mean[i];
}

struct XF {
    float l00, l10, l11, l20, l21, l22, l30, l31, l32, l33, m0, m1, m2, m3;
    __device__ __forceinline__ void load(const float* s) {
        l00 = s[0]; l10 = s[1]; l11 = s[2]; l20 = s[3]; l21 = s[4];
        l22 = s[5]; l30 = s[6]; l31 = s[7]; l32 = s[8]; l33 = s[9];
        m0 = s[10]; m1 = s[11]; m2 = s[12]; m3 = s[13];
    }
    __device__ __forceinline__ void apply(float4 z, float& s0, float& s1,
                                          float& s2, float& s3) const {
        s0 = fmaf(z.x, l00, m0);
        s1 = fmaf(z.y, l11, fmaf(z.x, l10, m1));
        s2 = fmaf(z.z, l22, fmaf(z.y, l21, fmaf(z.x, l20, m2)));
        s3 = fmaf(z.w, l33, fmaf(z.z, l32, fmaf(z.y, l31, fmaf(z.x, l30, m3))));
    }
};

// ---------------- kernel 1: moments + min/max of q and r ----------------
__global__ void __launch_bounds__(256) k_stats(const float2* __restrict__ q,
                                               const float2* __restrict__ r, int n) {
    int idx = blockIdx.x * blockDim.x + threadIdx.x;
    int stride = gridDim.x * blockDim.x;
    double s[14];
#pragma unroll
    for (int k = 0; k < 14; k++) s[k] = 0.0;
    unsigned mnq = 0xFFFFFFFFu, mxq = 0u, mnr = 0xFFFFFFFFu, mxr = 0u;

    for (int i = idx; i < n; i += stride) {
        float2 qv = q[i];
        float2 rv = r[i];
        double x0 = qv.x, x1 = qv.y, x2 = rv.x, x3 = rv.y;
        s[0] += x0; s[1] += x1; s[2] += x2; s[3] += x3;
        s[4]  += x0 * x0; s[5]  += x0 * x1; s[6]  += x0 * x2; s[7]  += x0 * x3;
        s[8]  += x1 * x1; s[9]  += x1 * x2; s[10] += x1 * x3;
        s[11] += x2 * x2; s[12] += x2 * x3; s[13] += x3 * x3;
        unsigned e;
        e = fenc(qv.x); mnq = min(mnq, e); mxq = max(mxq, e);
        e = fenc(qv.y); mnq = min(mnq, e); mxq = max(mxq, e);
        e = fenc(rv.x); mnr = min(mnr, e); mxr = max(mxr, e);
        e = fenc(rv.y); mnr = min(mnr, e); mxr = max(mxr, e);
    }

    const unsigned FULL = 0xFFFFFFFFu;
#pragma unroll
    for (int k = 0; k < 14; k++)
        for (int off = 16; off; off >>= 1) s[k] += __shfl_down_sync(FULL, s[k], off);
    for (int off = 16; off; off >>= 1) {
        mnq = min(mnq, __shfl_down_sync(FULL, mnq, off));
        mxq = max(mxq, __shfl_down_sync(FULL, mxq, off));
        mnr = min(mnr, __shfl_down_sync(FULL, mnr, off));
        mxr = max(mxr, __shfl_down_sync(FULL, mxr, off));
    }

    __shared__ double   sh[8][14];
    __shared__ unsigned shm[8][4];
    int wid = threadIdx.x >> 5, lane = threadIdx.x & 31;
    if (lane == 0) {
#pragma unroll
        for (int k = 0; k < 14; k++) sh[wid][k] = s[k];
        shm[wid][0] = mnq; shm[wid][1] = mxq; shm[wid][2] = mnr; shm[wid][3] = mxr;
    }
    __syncthreads();
    if (threadIdx.x == 0) {
        int nw = blockDim.x >> 5;
        for (int w = 1; w < nw; w++) {
#pragma unroll
            for (int k = 0; k < 14; k++) sh[0][k] += sh[w][k];
            shm[0][0] = min(shm[0][0], shm[w][0]);
            shm[0][1] = max(shm[0][1], shm[w][1]);
            shm[0][2] = min(shm[0][2], shm[w][2]);
            shm[0][3] = max(shm[0][3], shm[w][3]);
        }
#pragma unroll
        for (int k = 0; k < 14; k++) atomicAdd(&g_sums[k], sh[0][k]);
        atomicMin(&g_minq, shm[0][0]); atomicMax(&g_maxq, shm[0][1]);
        atomicMin(&g_minr, shm[0][2]); atomicMax(&g_maxr, shm[0][3]);
    }
}

// ---------------- kernel 2: marginal hists (blocks<MH) + sample min/max ----------------
__global__ void __launch_bounds__(256) k_phase2(const float2* __restrict__ q,
                                                const float2* __restrict__ r,
                                                const float4* __restrict__ z,
                                                int n, int S) {
    if (blockIdx.x < MH_BLOCKS) {
        // ---- marginal histograms, shared-memory privatized ----
        __shared__ unsigned shq[MBINS];
        __shared__ unsigned shr[MBINS];
        for (int i = threadIdx.x; i < MBINS; i += blockDim.x) { shq[i] = 0u; shr[i] = 0u; }
        __syncthreads();

        float loq = fdec(g_minq), hiq = fdec(g_maxq);
        float lor = fdec(g_minr), hir = fdec(g_maxr);
        float sq = (float)BINS / (hiq - loq);
        float sr = (float)BINS / (hir - lor);

        int idx = blockIdx.x * blockDim.x + threadIdx.x;
        int stride = MH_BLOCKS * blockDim.x;
        for (int i = idx; i < n; i += stride) {
            float2 qv = q[i];
            atomicAdd(&shq[binof(qv.x, loq, sq) * BINS + binof(qv.y, loq, sq)], 1u);
            float2 rv = r[i];
            atomicAdd(&shr[binof(rv.x, lor, sr) * BINS + binof(rv.y, lor, sr)], 1u);
        }
        __syncthreads();
        for (int i = threadIdx.x; i < MBINS; i += blockDim.x) {
            unsigned a = shq[i]; if (a) atomicAdd(&g_hist_q[i], a);
            unsigned b = shr[i]; if (b) atomicAdd(&g_hist_r[i], b);
        }
        return;
    }

    // ---- transform + global min/max of samples (MLP=4 batched loads) ----
    __shared__ float sP[14];
    if (threadIdx.x == 0) chol_from_sums(sP, (double)n);
    __syncthreads();
    XF xf; xf.load(sP);

    unsigned mn = 0xFFFFFFFFu, mx = 0u;
    int idx = (blockIdx.x - MH_BLOCKS) * blockDim.x + threadIdx.x;
    int stride = (P2_BLOCKS - MH_BLOCKS) * blockDim.x;

    int i = idx;
    for (; i + 3 * stride < S; i += 4 * stride) {
        float4 a = z[i];
        float4 b = z[i + stride];
        float4 c = z[i + 2 * stride];
        float4 d = z[i + 3 * stride];
        float s0, s1, s2, s3;
        unsigned e;
        xf.apply(a, s0, s1, s2, s3);
        e = fenc(s0); mn = min(mn, e); mx = max(mx, e);
        e = fenc(s1); mn = min(mn, e); mx = max(mx, e);
        e = fenc(s2); mn = min(mn, e); mx = max(mx, e);
        e = fenc(s3); mn = min(mn, e); mx = max(mx, e);
        xf.apply(b, s0, s1, s2, s3);
        e = fenc(s0); mn = min(mn, e); mx = max(mx, e);
        e = fenc(s1); mn = min(mn, e); mx = max(mx, e);
        e = fenc(s2); mn = min(mn, e); mx = max(mx, e);
        e = fenc(s3); mn = min(mn, e); mx = max(mx, e);
        xf.apply(c, s0, s1, s2, s3);
        e = fenc(s0); mn = min(mn, e); mx = max(mx, e);
        e = fenc(s1); mn = min(mn, e); mx = max(mx, e);
        e = fenc(s2); mn = min(mn, e); mx = max(mx, e);
        e = fenc(s3); mn = min(mn, e); mx = max(mx, e);
        xf.apply(d, s0, s1, s2, s3);
        e = fenc(s0); mn = min(mn, e); mx = max(mx, e);
        e = fenc(s1); mn = min(mn, e); mx = max(mx, e);
        e = fenc(s2); mn = min(mn, e); mx = max(mx, e);
        e = fenc(s3); mn = min(mn, e); mx = max(mx, e);
    }
    for (; i < S; i += stride) {
        float s0, s1, s2, s3;
        xf.apply(z[i], s0, s1, s2, s3);
        unsigned e;
        e = fenc(s0); mn = min(mn, e); mx = max(mx, e);
        e = fenc(s1); mn = min(mn, e); mx = max(mx, e);
        e = fenc(s2); mn = min(mn, e); mx = max(mx, e);
        e = fenc(s3); mn = min(mn, e); mx = max(mx, e);
    }

    const unsigned FULL = 0xFFFFFFFFu;
    for (int off = 16; off; off >>= 1) {
        mn = min(mn, __shfl_down_sync(FULL, mn, off));
        mx = max(mx, __shfl_down_sync(FULL, mx, off));
    }
    __shared__ unsigned shmn[8], shmx[8];
    int wid = threadIdx.x >> 5, lane = threadIdx.x & 31;
    if (lane == 0) { shmn[wid] = mn; shmx[wid] = mx; }
    __syncthreads();
    if (threadIdx.x == 0) {
        int nw = blockDim.x >> 5;
        for (int w = 1; w < nw; w++) { mn = min(mn, shmn[w]); mx = max(mx, shmx[w]); }
        atomicMin(&g_mins, mn);
        atomicMax(&g_maxs, mx);
    }
}

// ---------------- kernel 3: joint histogram (MLP=4) ----------------
__global__ void __launch_bounds__(256) k_jhist(const float4* __restrict__ z, int n, int S) {
    __shared__ float sP[14];
    if (threadIdx.x == 0) chol_from_sums(sP, (double)n);
    __syncthreads();
    XF xf; xf.load(sP);
    float lo = fdec(g_mins), hi = fdec(g_maxs);
    float sc = (float)BINS / (hi - lo);

    int idx = blockIdx.x * blockDim.x + threadIdx.x;
    int stride = gridDim.x * blockDim.x;

    int i = idx;
    for (; i + 3 * stride < S; i += 4 * stride) {
        float4 a = z[i];
        float4 b = z[i + stride];
        float4 c = z[i + 2 * stride];
        float4 d = z[i + 3 * stride];
        float s0, s1, s2, s3;
        xf.apply(a, s0, s1, s2, s3);
        int fa = ((binof(s0, lo, sc) * BINS + binof(s1, lo, sc)) * BINS +
                  binof(s2, lo, sc)) * BINS + binof(s3, lo, sc);
        xf.apply(b, s0, s1, s2, s3);
        int fb = ((binof(s0, lo, sc) * BINS + binof(s1, lo, sc)) * BINS +
                  binof(s2, lo, sc)) * BINS + binof(s3, lo, sc);
        xf.apply(c, s0, s1, s2, s3);
        int fc = ((binof(s0, lo, sc) * BINS + binof(s1, lo, sc)) * BINS +
                  binof(s2, lo, sc)) * BINS + binof(s3, lo, sc);
        xf.apply(d, s0, s1, s2, s3);
        int fd = ((binof(s0, lo, sc) * BINS + binof(s1, lo, sc)) * BINS +
                  binof(s2, lo, sc)) * BINS + binof(s3, lo, sc);
        atomicAdd(&g_hist_joint[fa], 1u);
        atomicAdd(&g_hist_joint[fb], 1u);
        atomicAdd(&g_hist_joint[fc], 1u);
        atomicAdd(&g_hist_joint[fd], 1u);
    }
    for (; i < S; i += stride) {
        float s0, s1, s2, s3;
        xf.apply(z[i], s0, s1, s2, s3);
        int f = ((binof(s0, lo, sc) * BINS + binof(s1, lo, sc)) * BINS +
                 binof(s2, lo, sc)) * BINS + binof(s3, lo, sc);
        atomicAdd(&g_hist_joint[f], 1u);
    }
}

// ---------------- kernel 4: joint entropy + finalization (last-block) ----------------
__global__ void __launch_bounds__(256) k_entJ(float* out, int n, int S) {
    double sum = 0.0;
    uint4* p = (uint4*)g_hist_joint;
    const uint4 zero = make_uint4(0u, 0u, 0u, 0u);
    int idx = blockIdx.x * blockDim.x + threadIdx.x;
    int stride = gridDim.x * blockDim.x;

    int i = idx;
    const int Q = JBINS / 4;
    for (; i + stride < Q; i += 2 * stride) {
        uint4 v = p[i];
        uint4 w = p[i + stride];
        if (v.x | v.y | v.z | v.w) {
            if (v.x) sum += (double)v.x * (double)logf((float)v.x);
            if (v.y) sum += (double)v.y * (double)logf((float)v.y);
            if (v.z) sum += (double)v.z * (double)logf((float)v.z);
            if (v.w) sum += (double)v.w * (double)logf((float)v.w);
            p[i] = zero;
        }
        if (w.x | w.y | w.z | w.w) {
            if (w.x) sum += (double)w.x * (double)logf((float)w.x);
            if (w.y) sum += (double)w.y * (double)logf((float)w.y);
            if (w.z) sum += (double)w.z * (double)logf((float)w.z);
            if (w.w) sum += (double)w.w * (double)logf((float)w.w);
            p[i + stride] = zero;
        }
    }
    for (; i < Q; i += stride) {
        uint4 v = p[i];
        if (v.x | v.y | v.z | v.w) {
            if (v.x) sum += (double)v.x * (double)logf((float)v.x);
            if (v.y) sum += (double)v.y * (double)logf((float)v.y);
            if (v.z) sum += (double)v.z * (double)logf((float)v.z);
            if (v.w) sum += (double)v.w * (double)logf((float)v.w);
            p[i] = zero;
        }
    }

    const unsigned FULL = 0xFFFFFFFFu;
    for (int off = 16; off; off >>= 1) sum += __shfl_down_sync(FULL, sum, off);
    __shared__ double sh[8];
    int wid = threadIdx.x >> 5, lane = threadIdx.x & 31;
    if (lane == 0) sh[wid] = sum;
    __syncthreads();
    __shared__ int s_last;
    if (threadIdx.x == 0) {
        int nw = blockDim.x >> 5;
        for (int w = 1; w < nw; w++) sum += sh[w];
        atomicAdd(&g_entJ, sum);
        __threadfence();
        unsigned t = atomicAdd(&g_done, 1u);
        s_last = (t == gridDim.x - 1) ? 1 : 0;
    }
    __syncthreads();
    if (!s_last) return;

    // ---- last block: marginal entropies + final scalar + state reset ----
    __threadfence();  // make all blocks' g_entJ contributions visible
    double sq = 0.0, sr = 0.0;
    for (int k = threadIdx.x; k < MBINS; k += blockDim.x) {
        unsigned a = g_hist_q[k]; if (a) { sq += (double)a * (double)logf((float)a); g_hist_q[k] = 0u; }
        unsigned b = g_hist_r[k]; if (b) { sr += (double)b * (double)logf((float)b); g_hist_r[k] = 0u; }
    }
    for (int off = 16; off; off >>= 1) {
        sq += __shfl_down_sync(FULL, sq, off);
        sr += __shfl_down_sync(FULL, sr, off);
    }
    __shared__ double shq[8], shr[8];
    if (lane == 0) { shq[wid] = sq; shr[wid] = sr; }
    __syncthreads();
    if (threadIdx.x == 0) {
        int nw = blockDim.x >> 5;
        for (int w = 1; w < nw; w++) { sq += shq[w]; sr += shr[w]; }
        double nn = (double)n, SS = (double)S;
        double H_T = log(nn) - sq / nn;
        double H_I = log(nn) - sr / nn;
        double H_J = log(SS) - g_entJ / SS;
        double v = H_J / (H_T + H_I);
        v = v < 0.0 ? 0.0 : (v > 1.0 ? 1.0 : v);
        out[0] = (float)v;

        // restore scalar state for the next replay
        g_entJ = 0.0;
#pragma unroll
        for (int k = 0; k < 14; k++) g_sums[k] = 0.0;
        g_minq = 0xFFFFFFFFu; g_maxq = 0u;
        g_minr = 0xFFFFFFFFu; g_maxr = 0u;
        g_mins = 0xFFFFFFFFu; g_maxs = 0u;
        g_done = 0u;
    }
}

// ---------------- launch ----------------
extern "C" void kernel_launch(void* const* d_in, const int* in_sizes, int n_in,
                              void* d_out, int out_size) {
    const float* q = (const float*)d_in[0];
    const float* r = (const float*)d_in[1];
    const float* z = (const float*)d_in[2];
    int n = in_sizes[0] / 2;   // 200000 rows of D=2
    int S = in_sizes[2] / 4;   // 2000000 rows of 2D=4

    k_stats<<<296, 256>>>((const float2*)q, (const float2*)r, n);
    k_phase2<<<P2_BLOCKS, 256>>>((const float2*)q, (const float2*)r,
                                 (const float4*)z, n, S);
    k_jhist<<<1184, 256>>>((const float4*)z, n, S);
    k_entJ<<<EJ_BLOCKS, 256>>>((float*)d_out, n, S);
}